// round 2
// baseline (speedup 1.0000x reference)
#include <cuda_runtime.h>

// ATCA/TCA loss, C = 10 (cluster gap window), single-pass per neuron.

#define CWIN 10

__global__ void atca_zero(float* out) { out[0] = 0.0f; }

__global__ void __launch_bounds__(128)
atca_kernel(const float* __restrict__ vmem, const int* __restrict__ labels,
            float* __restrict__ out, int BN, int T, int N)
{
    const int id = blockIdx.x * blockDim.x + threadIdx.x;
    float contrib = 0.0f;

    if (id < BN) {
        const int b = id / N;
        const int n = id - b * N;
        const float* __restrict__ p =
            vmem + (size_t)b * (size_t)T * (size_t)N + (size_t)n;

        const float NEG = -3.0e30f;

        float rb[16];                       // ring buffer of last 16 samples
        int   last_spike = -0x40000000;     // time of most recent spike
        float vmax = NEG; int tm = -1;      // global max + first argmax
        float v2   = NEG;                   // max over |s - tm| > C/2 (no-spike path)
        float m0   = NEG; int any_un = 0;   // max over unmasked times
        int   nc = 0;                       // cluster count
        float span_max = NEG;               // current cluster span max
        float gap_max  = NEG;               // max since last spike (exclusive)
        float total_rec = 0.0f;             // sum of finalized cluster maxima
        float top0 = NEG, top1 = NEG, top2 = NEG, top3 = NEG; // 4 largest maxima

        #pragma unroll 4
        for (int t = 0; t < T; ++t) {
            const float v = __ldg(p + (size_t)t * (size_t)N);
            rb[t & 15] = v;

            // ---- spike / cluster bookkeeping (causal) ----
            if (v >= 0.0f) {
                if (t - last_spike <= CWIN) {
                    // same cluster: span includes inter-spike gap values
                    span_max = fmaxf(span_max, fmaxf(gap_max, v));
                } else {
                    if (nc > 0) {
                        const float x = span_max;
                        total_rec += x;
                        if (x > top0)      { top3 = top2; top2 = top1; top1 = top0; top0 = x; }
                        else if (x > top1) { top3 = top2; top2 = top1; top1 = x; }
                        else if (x > top2) { top3 = top2; top2 = x; }
                        else if (x > top3) { top3 = x; }
                    }
                    ++nc;
                    span_max = v;
                }
                last_spike = t;
                gap_max = NEG;
            } else {
                gap_max = fmaxf(gap_max, v);
            }

            // ---- global max / first argmax, and v2 = max outside 11-window around tm ----
            if (v > vmax) {
                if (tm >= 0) {
                    if (t - tm > CWIN / 2) {
                        v2 = vmax;  // old best qualifies and dominates
                    } else {
                        // re-qualify buffered values near old tm: s in [t-CWIN, t-(CWIN/2+1)]
                        int s0 = t - CWIN; if (s0 < 0) s0 = 0;
                        for (int s = s0; s <= t - (CWIN / 2 + 1); ++s)
                            v2 = fmaxf(v2, rb[s & 15]);
                    }
                }
                vmax = v; tm = t;
            } else if (t - tm > CWIN / 2) {
                v2 = fmaxf(v2, v);
            }

            // ---- m0: finalize s = t - C (unmasked iff no spike in [s-C, s+C]) ----
            const int s = t - CWIN;
            if (s >= 0 && last_spike < t - 2 * CWIN) {
                m0 = fmaxf(m0, rb[s & 15]);
                any_un = 1;
            }
        }

        // finalize trailing cluster
        if (nc > 0) {
            const float x = span_max;
            total_rec += x;
            if (x > top0)      { top3 = top2; top2 = top1; top1 = top0; top0 = x; }
            else if (x > top1) { top3 = top2; top2 = top1; top1 = x; }
            else if (x > top2) { top3 = top2; top2 = x; }
            else if (x > top3) { top3 = x; }
        }
        // m0 tail: s in [T-C, T-1]
        {
            int s0 = T - CWIN; if (s0 < 0) s0 = 0;
            for (int s = s0; s < T; ++s) {
                if (last_spike < s - CWIN) {
                    m0 = fmaxf(m0, rb[s & 15]);
                    any_un = 1;
                }
            }
        }

        const int label = labels[id];
        if (label > nc) {
            // excess branch
            if (!any_un) {
                contrib = vmax;                      // full0: all times masked
            } else {
                float m_rest;
                if (nc > 0) {
                    // spikes exist -> tm is a spike -> win subset of mask -> mask2 == mask
                    m_rest = m0;
                } else {
                    // no spikes: mask2 = win around argmax; full2 iff win covers [0,T)
                    const bool full2 = (tm <= CWIN / 2) && (tm + CWIN / 2 >= T - 1);
                    m_rest = full2 ? vmax : v2;
                }
                const float dE = (float)(label - nc);     // >= 1 in this branch
                contrib = -((m0 + (dE - 1.0f) * m_rest) / dE);
            }
        } else if (label < nc) {
            // deficit branch: sum of (nc-label) smallest = total - top-`label` largest
            float ssum = total_rec;
            if (label >= 1) ssum -= top0;
            if (label >= 2) ssum -= top1;
            if (label >= 3) ssum -= top2;
            if (label >= 4) ssum -= top3;
            contrib = ssum / (float)(nc - label);
        }
        out[1 + id] = (float)nc;
    }

    // ---- block reduction of loss, one atomic per block ----
    float val = contrib;
    #pragma unroll
    for (int off = 16; off > 0; off >>= 1)
        val += __shfl_down_sync(0xffffffffu, val, off);
    __shared__ float ws[4];
    const int lane = threadIdx.x & 31;
    const int warp = threadIdx.x >> 5;
    if (lane == 0) ws[warp] = val;
    __syncthreads();
    if (threadIdx.x == 0)
        atomicAdd(out, ws[0] + ws[1] + ws[2] + ws[3]);
}

extern "C" void kernel_launch(void* const* d_in, const int* in_sizes, int n_in,
                              void* d_out, int out_size) {
    const float* vmem   = (const float*)d_in[0];
    // d_in[1] = vlastmem : unused by the reference forward
    const int*   labels = (const int*)d_in[2];
    // d_in[3] = ratio    : unused
    float* out = (float*)d_out;

    const int BN = in_sizes[2];           // B*N = 32768
    const int T  = in_sizes[0] / BN;      // 500
    const int N  = 128;                   // fixed problem shape

    atca_zero<<<1, 1>>>(out);

    const int threads = 128;
    const int blocks  = (BN + threads - 1) / threads;
    atca_kernel<<<blocks, threads>>>(vmem, labels, out, BN, T, N);
}

// round 3
// speedup vs baseline: 2.2401x; 2.2401x over previous
#include <cuda_runtime.h>

// ATCA/TCA loss, C = 10. Branchless single-pass scan, fully register-resident.

#define CWIN 10

__global__ void atca_zero(float* out) { out[0] = 0.0f; }

__global__ void __launch_bounds__(128)
atca_kernel(const float* __restrict__ vmem, const int* __restrict__ labels,
            float* __restrict__ out, int BN, int T, int N)
{
    const int id = blockIdx.x * blockDim.x + threadIdx.x;
    float contrib = 0.0f;

    if (id < BN) {
        const int b = id / N;
        const int n = id - b * N;
        const float* __restrict__ p =
            vmem + (size_t)b * (size_t)T * (size_t)N + (size_t)n;

        const float NEG = -3.0e30f;

        // scan state
        int   last_spike = -0x40000000;
        int   nc = 0;
        float vmax = NEG;
        float m0 = NEG;
        int   any_un = 0;
        float span_max = NEG;   // current cluster span max
        float gap_max  = NEG;   // max since last spike (exclusive)
        float total_rec = 0.0f; // sum of finalized cluster maxima
        float top0 = NEG, top1 = NEG, top2 = NEG, top3 = NEG;

        // pad time axis: run t in [0, Tp) with v=NEG for t>=T (spike-free,
        // max-neutral); this folds the m0 tail (s in [T-C, T)) into the loop.
        const int Tp = ((T + CWIN + 15) / 16) * 16;

        float cur[16], prv[16];
        #pragma unroll
        for (int k = 0; k < 16; ++k) prv[k] = NEG;

        for (int t0 = 0; t0 < Tp; t0 += 16) {
            // front-batched independent loads (MLP ~16)
            #pragma unroll
            for (int k = 0; k < 16; ++k) {
                const int t = t0 + k;
                cur[k] = (t < T) ? __ldg(p + (size_t)t * (size_t)N) : NEG;
            }
            #pragma unroll
            for (int k = 0; k < 16; ++k) {
                const int t = t0 + k;
                const float v = cur[k];
                const float vlag = (k >= CWIN) ? cur[k - CWIN] : prv[k + 16 - CWIN];

                const bool spk     = (v >= 0.0f);
                const bool new_clu = spk && (t - last_spike > CWIN);
                const bool fin     = new_clu && (nc > 0);
                const float x = fin ? span_max : NEG;     // value to retire
                total_rec += fin ? span_max : 0.0f;
                // sorted insert into descending top-4 (NEG insert = no-op)
                const float a0 = fmaxf(top0, x),  b0 = fminf(top0, x);
                const float a1 = fmaxf(top1, b0), b1 = fminf(top1, b0);
                const float a2 = fmaxf(top2, b1), b2 = fminf(top2, b1);
                const float a3 = fmaxf(top3, b2);
                top0 = a0; top1 = a1; top2 = a2; top3 = a3;

                nc += new_clu ? 1 : 0;
                const float g  = fmaxf(gap_max, v);
                const float se = fmaxf(span_max, g);
                span_max   = spk ? (new_clu ? v : se) : span_max;
                gap_max    = spk ? NEG : g;
                last_spike = spk ? t : last_spike;
                vmax = fmaxf(vmax, v);

                // finalize s = t - C: unmasked iff no spike in [s-C, s+C]
                const int s = t - CWIN;
                const bool um = (last_spike < t - 2 * CWIN) && (s >= 0) && (s < T);
                m0 = fmaxf(m0, um ? vlag : NEG);
                any_un |= um ? 1 : 0;
            }
            #pragma unroll
            for (int k = 0; k < 16; ++k) prv[k] = cur[k];
        }

        // retire the trailing cluster
        if (nc > 0) {
            const float x = span_max;
            total_rec += x;
            const float a0 = fmaxf(top0, x),  b0 = fminf(top0, x);
            const float a1 = fmaxf(top1, b0), b1 = fminf(top1, b0);
            const float a2 = fmaxf(top2, b1), b2 = fminf(top2, b1);
            const float a3 = fmaxf(top3, b2);
            top0 = a0; top1 = a1; top2 = a2; top3 = a3;
        }

        const int label = labels[id];
        if (label > nc) {
            if (!any_un) {
                contrib = vmax;                       // full0: everything masked
            } else {
                float m_rest;
                if (nc > 0) {
                    // spikes exist -> argmax is a spike -> mask2 == mask -> m_rest = m0
                    m_rest = m0;
                } else {
                    // cold path: no spikes at all. Recompute argmax window max.
                    int tm = 0; float vm = NEG;
                    for (int t = 0; t < T; ++t) {
                        const float v = __ldg(p + (size_t)t * (size_t)N);
                        if (v > vm) { vm = v; tm = t; }
                    }
                    float v2 = NEG;
                    for (int t = 0; t < T; ++t) {
                        if (t < tm - CWIN / 2 || t > tm + CWIN / 2)
                            v2 = fmaxf(v2, __ldg(p + (size_t)t * (size_t)N));
                    }
                    const bool full2 = (tm <= CWIN / 2) && (tm + CWIN / 2 >= T - 1);
                    m_rest = full2 ? vmax : v2;
                }
                const float dE = (float)(label - nc);  // >= 1 here
                contrib = -((m0 + (dE - 1.0f) * m_rest) / dE);
            }
        } else if (label < nc) {
            // sum of (nc-label) smallest = total - top-`label` largest (label<=4)
            float ssum = total_rec;
            if (label >= 1) ssum -= top0;
            if (label >= 2) ssum -= top1;
            if (label >= 3) ssum -= top2;
            if (label >= 4) ssum -= top3;
            contrib = ssum / (float)(nc - label);
        }
        out[1 + id] = (float)nc;
    }

    // block reduction of loss, one atomic per block
    float val = contrib;
    #pragma unroll
    for (int off = 16; off > 0; off >>= 1)
        val += __shfl_down_sync(0xffffffffu, val, off);
    __shared__ float ws[4];
    const int lane = threadIdx.x & 31;
    const int warp = threadIdx.x >> 5;
    if (lane == 0) ws[warp] = val;
    __syncthreads();
    if (threadIdx.x == 0)
        atomicAdd(out, ws[0] + ws[1] + ws[2] + ws[3]);
}

extern "C" void kernel_launch(void* const* d_in, const int* in_sizes, int n_in,
                              void* d_out, int out_size) {
    const float* vmem   = (const float*)d_in[0];
    const int*   labels = (const int*)d_in[2];
    float* out = (float*)d_out;

    const int BN = in_sizes[2];           // B*N = 32768
    const int T  = in_sizes[0] / BN;      // 500
    const int N  = 128;

    atca_zero<<<1, 1>>>(out);

    const int threads = 128;
    const int blocks  = (BN + threads - 1) / threads;
    atca_kernel<<<blocks, threads>>>(vmem, labels, out, BN, T, N);
}